// round 16
// baseline (speedup 1.0000x reference)
#include <cuda_runtime.h>
#include <cstdint>

#define N_DIST 1024
#define DIM    128
#define HID    256
#define NCHUNK 148
#define NQUAD  37
#define BATCH  256            // rows per staged batch
#define GDIM   32             // dims per group
#define CHUNKR 3379           // ceil(500000 / 148)

#define TABLE_B  (N_DIST * GDIM * 4)        // 131072
#define STAGE_B  (BATCH * GDIM * 4)         // 32768
#define ZS_OFF   (TABLE_B + 2 * STAGE_B)    // 196608
#define SMEM_ACC (ZS_OFF + 2 * BATCH * 4)   // 198656

// Scratch (no allocations). Counters are epoch-relative monotonic (graph-replay safe).
__device__ float g_part[NCHUNK][N_DIST * GDIM];   // 19 MB partial tables
__device__ int   g_qbar[NQUAD];                   // +16 per launch
__device__ int   g_rdone;                         // +128 per launch
__device__ int   g_epoch;                         // +1 per launch

// ================================================================ accumulate
// 148 blocks (1/SM), 256 threads. Block b: quad q=b>>2, dim-group g=b&3.
// Quad q streams chunks 4q..4q+3; in round r all 4 blocks read chunk 4q+r
// concurrently (each its 128B dim-slice) so DRAM pages are fully covered.
__global__ void __launch_bounds__(256, 1) k_accum(
    const float4* __restrict__ x4, const int* __restrict__ zone, int n)
{
    extern __shared__ char sm[];
    float*  table  = (float*)sm;
    float4* stg[2] = { (float4*)(sm + TABLE_B), (float4*)(sm + TABLE_B + STAGE_B) };
    int*    zs[2]  = { (int*)(sm + ZS_OFF), (int*)(sm + ZS_OFF + BATCH * 4) };
    __shared__ int sh_e;

    int b = blockIdx.x, t = threadIdx.x;
    int q = b >> 2, g = b & 3;
    int lane = t & 31, w = t >> 5;

    if (t == 0) sh_e = *(volatile int*)&g_epoch;
    for (int i = t; i < N_DIST * GDIM / 4; i += 256)
        ((float4*)table)[i] = make_float4(0.f, 0.f, 0.f, 0.f);
    __syncthreads();
    int E = sh_e;

    for (int r = 0; r < 4; r++) {
        int c  = q * 4 + r;
        int rs = c * CHUNKR;
        int re = min(n, rs + CHUNKR);
        int nb = (re - rs + BATCH - 1) / BATCH;
        int buf = 0;

        // prefetch batch 0 into registers
        float4 v[8];
        int myz;
        {
            #pragma unroll
            for (int i = 0; i < 8; i++) {
                int elem = t + 256 * i;
                int row  = rs + (elem >> 3);
                v[i] = (row < re) ? x4[(size_t)row * 32 + g * 8 + (elem & 7)]
                                  : make_float4(0.f, 0.f, 0.f, 0.f);
            }
            int zr = rs + t;
            myz = (zr < re) ? zone[zr] : -1;
        }

        for (int k = 0; k < nb; k++) {
            __syncthreads();                       // stage[buf] free (processed 2 iters ago)
            #pragma unroll
            for (int i = 0; i < 8; i++)
                stg[buf][t + 256 * i] = v[i];
            zs[buf][t] = myz;
            __syncthreads();

            // prefetch next batch (overlaps with processing below)
            if (k + 1 < nb) {
                int base = rs + (k + 1) * BATCH;
                #pragma unroll
                for (int i = 0; i < 8; i++) {
                    int elem = t + 256 * i;
                    int row  = base + (elem >> 3);
                    v[i] = (row < re) ? x4[(size_t)row * 32 + g * 8 + (elem & 7)]
                                      : make_float4(0.f, 0.f, 0.f, 0.f);
                }
                int zr = base + t;
                myz = (zr < re) ? zone[zr] : -1;
            }

            // process stage[buf]: warp w owns rows with (z & 7) == w; lane = dim
            const float* sf = (const float*)stg[buf];
            #pragma unroll
            for (int blk = 0; blk < 2; blk++) {
                int4 zz = ((const int4*)zs[buf])[lane + 32 * blk];
                #pragma unroll
                for (int s = 0; s < 4; s++) {
                    int z = (s == 0) ? zz.x : (s == 1) ? zz.y : (s == 2) ? zz.z : zz.w;
                    unsigned mask = __ballot_sync(0xffffffffu, z >= 0 && (z & 7) == w);
                    while (mask) {
                        int p = __ffs(mask) - 1;
                        mask &= mask - 1;
                        int zr = __shfl_sync(0xffffffffu, z, p);
                        int j  = ((blk * 32 + p) << 2) + s;
                        table[zr * GDIM + lane] += sf[j * GDIM + lane];
                    }
                }
            }
            buf ^= 1;
        }

        // quad pacing barrier at chunk boundary (keeps the 4 slices in lockstep)
        __syncthreads();
        if (t == 0) {
            __threadfence();
            atomicAdd(&g_qbar[q], 1);
            int target = E * 16 + (r + 1) * 4;
            while (*(volatile int*)&g_qbar[q] < target) __nanosleep(64);
        }
        __syncthreads();
    }

    // flush table to global partials (coalesced)
    for (int i = t; i < N_DIST * GDIM / 4; i += 256)
        ((float4*)&g_part[b][0])[i] = ((const float4*)table)[i];
}

// ================================================================ reduce + ReLU + MLP
// 128 blocks x 256 threads, 8 districts per block.
__global__ void __launch_bounds__(256) k_reduce_mlp(
    const float* __restrict__ w1, const float* __restrict__ b1,
    const float* __restrict__ w2, const float* __restrict__ b2,
    float* __restrict__ out)
{
    __shared__ float sh_head[8][DIM];
    __shared__ float sh_h1[8][HID];
    int blk = blockIdx.x, t = threadIdx.x;
    int dbase = blk * 8;

    #pragma unroll
    for (int i = 0; i < 4; i++) {
        int idx = t + 256 * i;            // 0..1023 = (district_local, dim)
        int dl = idx >> 7, k = idx & 127;
        int g = k >> 5, col = k & 31;
        int d = dbase + dl;
        float sum = 0.f;
        #pragma unroll 4
        for (int qq = 0; qq < NQUAD; qq++)
            sum += g_part[(qq << 2) | g][d * GDIM + col];
        sh_head[dl][k] = fmaxf(sum, 0.f);
    }
    __syncthreads();

    {   // Phase A: h1 = relu(head @ w1 + b1), thread t = hidden column
        int col = t;
        float accm[8];
        float bb = b1[col];
        #pragma unroll
        for (int r = 0; r < 8; r++) accm[r] = bb;
        #pragma unroll 4
        for (int k = 0; k < DIM; k++) {
            float wv = w1[k * HID + col];
            #pragma unroll
            for (int r = 0; r < 8; r++) accm[r] += sh_head[r][k] * wv;
        }
        #pragma unroll
        for (int r = 0; r < 8; r++) sh_h1[r][col] = fmaxf(accm[r], 0.f);
    }
    __syncthreads();

    {   // Phase B: out = h1 @ w2 + b2
        int col = t & 127;
        int r0  = (t >> 7) * 4;
        float accm[4];
        float bb = b2[col];
        #pragma unroll
        for (int r = 0; r < 4; r++) accm[r] = bb;
        #pragma unroll 4
        for (int k = 0; k < HID; k++) {
            float wv = w2[k * DIM + col];
            #pragma unroll
            for (int r = 0; r < 4; r++) accm[r] += sh_h1[r0 + r][k] * wv;
        }
        #pragma unroll
        for (int r = 0; r < 4; r++)
            out[(size_t)(dbase + r0 + r) * DIM + col] = accm[r];
    }

    __threadfence();
    if (t == 0) {
        int old = atomicAdd(&g_rdone, 1);
        if (((old + 1) & 127) == 0) atomicAdd(&g_epoch, 1);   // once per launch
    }
}

// ---------------------------------------------------------------- launch
extern "C" void kernel_launch(void* const* d_in, const int* in_sizes, int n_in,
                              void* d_out, int out_size) {
    const float* x    = (const float*)d_in[0];
    const int*   zone = (const int*)d_in[1];
    const float* w1   = (const float*)d_in[2];
    const float* b1   = (const float*)d_in[3];
    const float* w2   = (const float*)d_in[4];
    const float* b2   = (const float*)d_in[5];
    float*       out  = (float*)d_out;
    int n = in_sizes[1];                 // 500000

    cudaFuncSetAttribute(k_accum, cudaFuncAttributeMaxDynamicSharedMemorySize, SMEM_ACC);

    k_accum     <<<NCHUNK, 256, SMEM_ACC>>>((const float4*)x, zone, n);
    k_reduce_mlp<<<128, 256>>>(w1, b1, w2, b2, out);
}

// round 17
// speedup vs baseline: 3.5161x; 3.5161x over previous
#include <cuda_runtime.h>

#define N_DIST 1024
#define DIM    128
#define HID    256
#define MAXN   500000
#define NBLK   512
#define GCHUNK 2048
#define NGROUP (N_DIST / 8)

// Scratch (no allocations allowed) — fully rewritten every launch.
__device__ int   g_counts[N_DIST * NBLK];   // [d][b]  (hist writes strided, scan reads coalesced)
__device__ int   g_bcursor[NBLK * N_DIST];  // [b][d]  (scan writes strided, scatter reads coalesced)
__device__ int   g_total[N_DIST];
__device__ int   g_offsets[N_DIST + 1];
__device__ int   g_order[MAXN];
__device__ float g_heads[2][N_DIST * DIM];
__device__ int   g_done[NGROUP];            // reset each launch by k_hist block 0

// ---------------------------------------------------------------- A: per-block histogram
__global__ void __launch_bounds__(256) k_hist(const int4* __restrict__ zone4, int n4, int chunk4) {
    __shared__ int sh[N_DIST];
    int b = blockIdx.x, t = threadIdx.x;
    if (b == 0 && t < NGROUP) g_done[t] = 0;     // reset completion counters each launch
    for (int i = t; i < N_DIST; i += 256) sh[i] = 0;
    __syncthreads();
    int s = b * chunk4, e = min(n4, s + chunk4);
    for (int i = s + t; i < e; i += 256) {
        int4 z = zone4[i];
        atomicAdd(&sh[z.x], 1);
        atomicAdd(&sh[z.y], 1);
        atomicAdd(&sh[z.z], 1);
        atomicAdd(&sh[z.w], 1);
    }
    __syncthreads();
    for (int i = t; i < N_DIST; i += 256)
        g_counts[i * NBLK + b] = sh[i];          // strided write (hidden)
}

// ---------------------------------------------------------------- B: scan over blocks per district (shfl-based)
__global__ void __launch_bounds__(NBLK) k_scan_blocks() {
    __shared__ int warp_part[16];
    int d = blockIdx.x, t = threadIdx.x;
    int lane = t & 31, w = t >> 5;
    int c = g_counts[d * NBLK + t];              // coalesced read
    int inc = c;
    #pragma unroll
    for (int o = 1; o < 32; o <<= 1) {
        int v = __shfl_up_sync(0xffffffffu, inc, o);
        if (lane >= o) inc += v;
    }
    if (lane == 31) warp_part[w] = inc;
    __syncthreads();
    if (t < 32) {
        int v = (t < 16) ? warp_part[t] : 0;
        #pragma unroll
        for (int o = 1; o < 16; o <<= 1) {
            int u = __shfl_up_sync(0xffffffffu, v, o);
            if (lane >= o) v += u;
        }
        if (t < 16) warp_part[t] = v;
    }
    __syncthreads();
    int base = (w > 0) ? warp_part[w - 1] : 0;
    g_bcursor[t * N_DIST + d] = base + inc - c;  // exclusive within district (strided write)
    if (t == NBLK - 1) g_total[d] = base + inc;
}

// ---------------------------------------------------------------- C: scatter (inline district scan + smem atomics)
__global__ void __launch_bounds__(256) k_scatter(const int4* __restrict__ zone4, int n4, int chunk4) {
    __shared__ int cur[N_DIST];
    __shared__ int warp_part[8];
    int b = blockIdx.x, t = threadIdx.x;
    int lane = t & 31, w = t >> 5;

    // --- inline exclusive scan of g_total (1024 elems, 4 per thread) ---
    int4 tt = ((const int4*)g_total)[t];
    int mysum = tt.x + tt.y + tt.z + tt.w;
    int inc = mysum;
    #pragma unroll
    for (int o = 1; o < 32; o <<= 1) {
        int v = __shfl_up_sync(0xffffffffu, inc, o);
        if (lane >= o) inc += v;
    }
    if (lane == 31) warp_part[w] = inc;
    __syncthreads();
    if (t == 0) {
        int run = 0;
        #pragma unroll
        for (int i = 0; i < 8; i++) { int v = warp_part[i]; warp_part[i] = run; run += v; }
    }
    __syncthreads();
    int e0 = warp_part[w] + (inc - mysum);
    int e1 = e0 + tt.x, e2 = e1 + tt.y, e3 = e2 + tt.z;

    if (b == 0) {                                 // publish offsets for gather
        g_offsets[4 * t + 0] = e0;
        g_offsets[4 * t + 1] = e1;
        g_offsets[4 * t + 2] = e2;
        g_offsets[4 * t + 3] = e3;
        if (t == 255) g_offsets[N_DIST] = e3 + tt.w;
    }

    int4 bc = ((const int4*)g_bcursor)[b * (N_DIST / 4) + t];   // coalesced
    cur[4 * t + 0] = e0 + bc.x;
    cur[4 * t + 1] = e1 + bc.y;
    cur[4 * t + 2] = e2 + bc.z;
    cur[4 * t + 3] = e3 + bc.w;
    __syncthreads();

    int s = b * chunk4, e = min(n4, s + chunk4);
    for (int i = s + t; i < e; i += 256) {
        int4 z = zone4[i];
        int p0 = atomicAdd(&cur[z.x], 1);
        int p1 = atomicAdd(&cur[z.y], 1);
        int p2 = atomicAdd(&cur[z.z], 1);
        int p3 = atomicAdd(&cur[z.w], 1);
        int i0 = i * 4;
        g_order[p0] = i0;
        g_order[p1] = i0 + 1;
        g_order[p2] = i0 + 2;
        g_order[p3] = i0 + 3;
    }
}

// ---------------------------------------------------------------- D: gather (split-2) + fused MLP
// 2048 blocks: district d = blockIdx>>1, half h = blockIdx&1. 256 threads = 8 warps.
// Last-finishing block of each 8-district group runs the MLP for that group.
__global__ void __launch_bounds__(256) k_gather(
    const float4* __restrict__ x4,
    const float* __restrict__ w1, const float* __restrict__ b1,
    const float* __restrict__ w2, const float* __restrict__ b2,
    float* __restrict__ out)
{
    __shared__ __align__(16) char smem_buf[12 * 1024];
    int*   sh_idx  = (int*)smem_buf;                                  // 8KB (gather)
    float4 (*sh_part)[32] = (float4(*)[32])(smem_buf + 8192);         // 4KB (gather)
    float  (*sh_head)[DIM] = (float(*)[DIM])smem_buf;                 // 4KB (mlp)
    float  (*sh_h1)[HID]   = (float(*)[HID])(smem_buf + 4096);        // 8KB (mlp)
    __shared__ int sh_last;

    int bid = blockIdx.x;
    int d = bid >> 1, h = bid & 1;
    int t = threadIdx.x;
    int w = t >> 5, lane = t & 31;
    int s0 = g_offsets[d], e0 = g_offsets[d + 1];
    int cnt0 = e0 - s0;
    int half = (cnt0 + 1) >> 1;
    int s = s0 + (h ? half : 0);
    int e = h ? e0 : (s0 + half);
    int cnt = e - s;
    float4 acc = make_float4(0.f, 0.f, 0.f, 0.f);

    for (int base = 0; base < cnt; base += GCHUNK) {
        int m = min(GCHUNK, cnt - base);
        __syncthreads();
        for (int i = t; i < m; i += 256)
            sh_idx[i] = g_order[s + base + i];
        __syncthreads();

        int r = w;
        for (; r + 64 <= m; r += 64) {       // 8 warps x 8-way unroll
            float4 v[8];
            #pragma unroll
            for (int u = 0; u < 8; u++) {
                size_t p = (size_t)sh_idx[r + u * 8] * 32 + lane;
                v[u] = __ldcs(&x4[p]);
            }
            #pragma unroll
            for (int u = 0; u < 8; u++) {
                acc.x += v[u].x; acc.y += v[u].y;
                acc.z += v[u].z; acc.w += v[u].w;
            }
        }
        for (; r < m; r += 8) {
            float4 v = __ldcs(&x4[(size_t)sh_idx[r] * 32 + lane]);
            acc.x += v.x; acc.y += v.y; acc.z += v.z; acc.w += v.w;
        }
    }

    sh_part[w][lane] = acc;
    __syncthreads();
    if (w == 0) {
        float4 r = sh_part[0][lane];
        #pragma unroll
        for (int wi = 1; wi < 8; wi++) {
            float4 p = sh_part[wi][lane];
            r.x += p.x; r.y += p.y; r.z += p.z; r.w += p.w;
        }
        ((float4*)g_heads[h])[d * 32 + lane] = r;   // partial, no ReLU yet
        __threadfence();
    }
    __syncthreads();

    int grp = d >> 3;
    if (t == 0) sh_last = (atomicAdd(&g_done[grp], 1) == 15) ? 1 : 0;
    __syncthreads();
    if (!sh_last) return;
    __threadfence();

    // ---------------- fused MLP for this group's 8 districts ----------------
    int gbase = grp * 8;
    __syncthreads();   // smem reuse barrier
    for (int idx = t; idx < 8 * DIM; idx += 256) {
        float p = __ldcg(&g_heads[0][gbase * DIM + idx]) + __ldcg(&g_heads[1][gbase * DIM + idx]);
        sh_head[idx >> 7][idx & 127] = fmaxf(p, 0.f);
    }
    __syncthreads();

    {   // Phase A: h1 = relu(head @ w1 + b1), thread t = hidden column
        int col = t;
        float accm[8];
        float bb = b1[col];
        #pragma unroll
        for (int r = 0; r < 8; r++) accm[r] = bb;
        #pragma unroll 4
        for (int k = 0; k < DIM; k++) {
            float wv = w1[k * HID + col];
            #pragma unroll
            for (int r = 0; r < 8; r++) accm[r] += sh_head[r][k] * wv;
        }
        #pragma unroll
        for (int r = 0; r < 8; r++) sh_h1[r][col] = fmaxf(accm[r], 0.f);
    }
    __syncthreads();

    {   // Phase B: out = h1 @ w2 + b2
        int col = t & 127;
        int r0  = (t >> 7) * 4;
        float accm[4];
        float bb = b2[col];
        #pragma unroll
        for (int r = 0; r < 4; r++) accm[r] = bb;
        #pragma unroll 4
        for (int k = 0; k < HID; k++) {
            float wv = w2[k * DIM + col];
            #pragma unroll
            for (int r = 0; r < 4; r++) accm[r] += sh_h1[r0 + r][k] * wv;
        }
        #pragma unroll
        for (int r = 0; r < 4; r++)
            out[(size_t)(gbase + r0 + r) * DIM + col] = accm[r];
    }
}

// ---------------------------------------------------------------- launch
extern "C" void kernel_launch(void* const* d_in, const int* in_sizes, int n_in,
                              void* d_out, int out_size) {
    const float* x    = (const float*)d_in[0];
    const int*   zone = (const int*)d_in[1];
    const float* w1   = (const float*)d_in[2];
    const float* b1   = (const float*)d_in[3];
    const float* w2   = (const float*)d_in[4];
    const float* b2   = (const float*)d_in[5];
    float*       out  = (float*)d_out;
    int n  = in_sizes[1];                // 500000, divisible by 4
    int n4 = n / 4;
    int chunk4 = (n4 + NBLK - 1) / NBLK;

    k_hist       <<<NBLK, 256>>>((const int4*)zone, n4, chunk4);
    k_scan_blocks<<<N_DIST, NBLK>>>();
    k_scatter    <<<NBLK, 256>>>((const int4*)zone, n4, chunk4);
    k_gather     <<<N_DIST * 2, 256>>>((const float4*)x, w1, b1, w2, b2, out);
}